// round 10
// baseline (speedup 1.0000x reference)
#include <cuda_runtime.h>
#include <math.h>
#include <stdint.h>

#define B_    64
#define L_    197
#define D_    192
#define H_    3
#define DH_   64
#define MM_   128
#define TM_   256           // 2M
#define NT_   (B_*L_)       // 12608
#define NTP_  12672         // 99 * 128 (padded rows)
#define FF_   768
#define NCLS_ 1000
#define NP_   (B_*196)      // 12544
#define KVSZ  (B_*H_*DH_*TM_)   // 3145728
#define KSSZ  (B_*H_*TM_)       // 49152

// ---------------- scratch (static device globals; zero-initialized) ----------------
__device__ float g_xc [NTP_*D_];
__device__ float g_q  [NTP_*D_];
__device__ float g_k  [NTP_*D_];
__device__ float g_v  [NTP_*D_];
__device__ float g_Qp [NT_*H_*TM_];
__device__ float g_Kp [NT_*H_*TM_];
__device__ float g_KVp[4*KVSZ];          // 4 split partials, [s][bh][d][m]
__device__ float g_Ksp[4*KSSZ];          // [s][bh][m]
__device__ float g_at [NTP_*D_];
__device__ float g_tp [NTP_*D_];
__device__ float g_h1 [NTP_*FF_];
__device__ float g_pl [128*D_];
__device__ float g_im [NP_*768];
__device__ float g_omT[12*MM_*DH_];      // per-layer transposed, pre-scaled omega

__device__ __forceinline__ uint32_t f2tf(float f) {
    uint32_t o; asm("cvt.rna.tf32.f32 %0, %1;" : "=r"(o) : "f"(f)); return o;
}

#define MMA_TF32(acc, af, bf)                                               \
    asm volatile(                                                           \
        "mma.sync.aligned.m16n8k8.row.col.f32.tf32.tf32.f32 "               \
        "{%0,%1,%2,%3}, {%4,%5,%6,%7}, {%8,%9}, {%0,%1,%2,%3};\n"           \
        : "+f"(acc[0]), "+f"(acc[1]), "+f"(acc[2]), "+f"(acc[3])            \
        : "r"(af[0]), "r"(af[1]), "r"(af[2]), "r"(af[3]),                   \
          "r"(bf[0]), "r"(bf[1]))

// fragment loads from smem (pitch 36, conflict-free), 2x4 warp tile
#define LOAD_FRAGS(As, Ws, kb)                                              \
    uint32_t af[2][4], bf[4][2];                                            \
    _Pragma("unroll")                                                       \
    for (int fm = 0; fm < 2; fm++) {                                        \
        int r0 = warp_m * 32 + fm * 16 + gid;                               \
        af[fm][0] = As[r0 * 36 + kb + tg];                                  \
        af[fm][1] = As[(r0 + 8) * 36 + kb + tg];                            \
        af[fm][2] = As[r0 * 36 + kb + tg + 4];                              \
        af[fm][3] = As[(r0 + 8) * 36 + kb + tg + 4];                        \
    }                                                                       \
    _Pragma("unroll")                                                       \
    for (int fn = 0; fn < 4; fn++) {                                        \
        int n = warp_n * 32 + fn * 8 + gid;                                 \
        bf[fn][0] = Ws[n * 36 + kb + tg];                                   \
        bf[fn][1] = Ws[n * 36 + kb + tg + 4];                               \
    }

// ---------------- TF32 tensor-core GEMM (generic) ----------------
__global__ __launch_bounds__(256) void tgemm_kernel(
    const float* __restrict__ A, const float* __restrict__ W,
    const float* __restrict__ bias, const float* __restrict__ add,
    float* __restrict__ C, int K, int Mo, int Nstore, int relu)
{
    __shared__ __align__(16) uint32_t As[128*36];
    __shared__ __align__(16) uint32_t Ws[64*36];
    const int bm = blockIdx.y * 128;
    const int bn = blockIdx.x * 64;
    const int tid  = threadIdx.x;
    const int lane = tid & 31, wid = tid >> 5;
    const int warp_m = wid >> 1, warp_n = wid & 1;
    const int gid = lane >> 2, tg = lane & 3;

    float acc[2][4][4];
#pragma unroll
    for (int a = 0; a < 2; a++)
#pragma unroll
        for (int b = 0; b < 4; b++)
#pragma unroll
            for (int c = 0; c < 4; c++) acc[a][b][c] = 0.f;

    const int niter = K >> 5;
    float4 pa[4], pw[2];

#pragma unroll
    for (int p = 0; p < 4; p++) {
        int idx = tid + p * 256;
        int r = idx >> 3, c = (idx & 7) << 2;
        pa[p] = *reinterpret_cast<const float4*>(A + (size_t)(bm + r) * K + c);
    }
#pragma unroll
    for (int p = 0; p < 2; p++) {
        int idx = tid + p * 256;
        int r = idx >> 3, c = (idx & 7) << 2;
        int wr = bn + r;
        pw[p] = (wr < Mo) ? *reinterpret_cast<const float4*>(W + (size_t)wr * K + c)
                          : make_float4(0.f, 0.f, 0.f, 0.f);
    }

    for (int it = 0; it < niter; it++) {
#pragma unroll
        for (int p = 0; p < 4; p++) {
            int idx = tid + p * 256;
            int r = idx >> 3, c = (idx & 7) << 2;
            uint32_t* d = &As[r * 36 + c];
            d[0] = f2tf(pa[p].x); d[1] = f2tf(pa[p].y);
            d[2] = f2tf(pa[p].z); d[3] = f2tf(pa[p].w);
        }
#pragma unroll
        for (int p = 0; p < 2; p++) {
            int idx = tid + p * 256;
            int r = idx >> 3, c = (idx & 7) << 2;
            uint32_t* d = &Ws[r * 36 + c];
            d[0] = f2tf(pw[p].x); d[1] = f2tf(pw[p].y);
            d[2] = f2tf(pw[p].z); d[3] = f2tf(pw[p].w);
        }
        __syncthreads();

        if (it + 1 < niter) {
            int k0 = (it + 1) << 5;
#pragma unroll
            for (int p = 0; p < 4; p++) {
                int idx = tid + p * 256;
                int r = idx >> 3, c = (idx & 7) << 2;
                pa[p] = *reinterpret_cast<const float4*>(A + (size_t)(bm + r) * K + k0 + c);
            }
#pragma unroll
            for (int p = 0; p < 2; p++) {
                int idx = tid + p * 256;
                int r = idx >> 3, c = (idx & 7) << 2;
                int wr = bn + r;
                pw[p] = (wr < Mo) ? *reinterpret_cast<const float4*>(W + (size_t)wr * K + k0 + c)
                                  : make_float4(0.f, 0.f, 0.f, 0.f);
            }
        }

#pragma unroll
        for (int ks = 0; ks < 4; ks++) {
            const int kb = ks * 8;
            LOAD_FRAGS(As, Ws, kb)
#pragma unroll
            for (int fm = 0; fm < 2; fm++)
#pragma unroll
                for (int fn = 0; fn < 4; fn++) MMA_TF32(acc[fm][fn], af[fm], bf[fn]);
        }
        __syncthreads();
    }

#pragma unroll
    for (int fm = 0; fm < 2; fm++) {
        int rbase = bm + warp_m * 32 + fm * 16 + gid;
#pragma unroll
        for (int fn = 0; fn < 4; fn++) {
            int c = bn + warp_n * 32 + fn * 8 + (tg << 1);
            if (c < Mo) {
                float bc0 = bias[c], bc1 = bias[c + 1];
#pragma unroll
                for (int h = 0; h < 2; h++) {
                    int row = rbase + h * 8;
                    if (row < Nstore) {
                        float v0 = acc[fm][fn][h * 2 + 0] + bc0;
                        float v1 = acc[fm][fn][h * 2 + 1] + bc1;
                        if (add) {
                            float2 ad = *reinterpret_cast<const float2*>(add + (size_t)row * Mo + c);
                            v0 += ad.x; v1 += ad.y;
                        }
                        if (relu) { v0 = fmaxf(v0, 0.f); v1 = fmaxf(v1, 0.f); }
                        *reinterpret_cast<float2*>(C + (size_t)row * Mo + c) = make_float2(v0, v1);
                    }
                }
            }
        }
    }
}

// ---------------- fused QKV GEMM: grid (9, 99) ----------------
__global__ __launch_bounds__(256) void qkv_gemm_kernel(
    const float* __restrict__ A,
    const float* __restrict__ Wq, const float* __restrict__ Wk, const float* __restrict__ Wv,
    const float* __restrict__ bq, const float* __restrict__ bk, const float* __restrict__ bv,
    float* __restrict__ Qo, float* __restrict__ Ko, float* __restrict__ Vo)
{
    __shared__ __align__(16) uint32_t As[128*36];
    __shared__ __align__(16) uint32_t Ws[64*36];
    const int sel = blockIdx.x / 3;
    const int bn  = (blockIdx.x % 3) * 64;
    const float* W    = (sel == 0) ? Wq : (sel == 1) ? Wk : Wv;
    const float* bias = (sel == 0) ? bq : (sel == 1) ? bk : bv;
    float* C          = (sel == 0) ? Qo : (sel == 1) ? Ko : Vo;

    const int bm = blockIdx.y * 128;
    const int tid  = threadIdx.x;
    const int lane = tid & 31, wid = tid >> 5;
    const int warp_m = wid >> 1, warp_n = wid & 1;
    const int gid = lane >> 2, tg = lane & 3;

    float acc[2][4][4];
#pragma unroll
    for (int a = 0; a < 2; a++)
#pragma unroll
        for (int b = 0; b < 4; b++)
#pragma unroll
            for (int c = 0; c < 4; c++) acc[a][b][c] = 0.f;

    float4 pa[4], pw[2];
#pragma unroll
    for (int p = 0; p < 4; p++) {
        int idx = tid + p * 256;
        int r = idx >> 3, c = (idx & 7) << 2;
        pa[p] = *reinterpret_cast<const float4*>(A + (size_t)(bm + r) * D_ + c);
    }
#pragma unroll
    for (int p = 0; p < 2; p++) {
        int idx = tid + p * 256;
        int r = idx >> 3, c = (idx & 7) << 2;
        pw[p] = *reinterpret_cast<const float4*>(W + (size_t)(bn + r) * D_ + c);
    }

    for (int it = 0; it < 6; it++) {
#pragma unroll
        for (int p = 0; p < 4; p++) {
            int idx = tid + p * 256;
            int r = idx >> 3, c = (idx & 7) << 2;
            uint32_t* d = &As[r * 36 + c];
            d[0] = f2tf(pa[p].x); d[1] = f2tf(pa[p].y);
            d[2] = f2tf(pa[p].z); d[3] = f2tf(pa[p].w);
        }
#pragma unroll
        for (int p = 0; p < 2; p++) {
            int idx = tid + p * 256;
            int r = idx >> 3, c = (idx & 7) << 2;
            uint32_t* d = &Ws[r * 36 + c];
            d[0] = f2tf(pw[p].x); d[1] = f2tf(pw[p].y);
            d[2] = f2tf(pw[p].z); d[3] = f2tf(pw[p].w);
        }
        __syncthreads();

        if (it + 1 < 6) {
            int k0 = (it + 1) << 5;
#pragma unroll
            for (int p = 0; p < 4; p++) {
                int idx = tid + p * 256;
                int r = idx >> 3, c = (idx & 7) << 2;
                pa[p] = *reinterpret_cast<const float4*>(A + (size_t)(bm + r) * D_ + k0 + c);
            }
#pragma unroll
            for (int p = 0; p < 2; p++) {
                int idx = tid + p * 256;
                int r = idx >> 3, c = (idx & 7) << 2;
                pw[p] = *reinterpret_cast<const float4*>(W + (size_t)(bn + r) * D_ + k0 + c);
            }
        }

#pragma unroll
        for (int ks = 0; ks < 4; ks++) {
            const int kb = ks * 8;
            LOAD_FRAGS(As, Ws, kb)
#pragma unroll
            for (int fm = 0; fm < 2; fm++)
#pragma unroll
                for (int fn = 0; fn < 4; fn++) MMA_TF32(acc[fm][fn], af[fm], bf[fn]);
        }
        __syncthreads();
    }

#pragma unroll
    for (int fm = 0; fm < 2; fm++) {
        int rbase = bm + warp_m * 32 + fm * 16 + gid;
#pragma unroll
        for (int fn = 0; fn < 4; fn++) {
            int c = bn + warp_n * 32 + fn * 8 + (tg << 1);
            float bc0 = bias[c], bc1 = bias[c + 1];
#pragma unroll
            for (int h = 0; h < 2; h++) {
                int row = rbase + h * 8;
                *reinterpret_cast<float2*>(C + (size_t)row * D_ + c) =
                    make_float2(acc[fm][fn][h * 2 + 0] + bc0, acc[fm][fn][h * 2 + 1] + bc1);
            }
        }
    }
}

// ---------------- FAVOR feature-map GEMM (N=128 tile, offs fused) ----------------
// grid (99, 6): y%3 = head, y/3 selects (q->Qp) or (k->Kp). M-tile 128, N=128, K=64.
__global__ __launch_bounds__(256) void favor_gemm_kernel(
    const float* __restrict__ Qin, const float* __restrict__ Kin,
    const float* __restrict__ omT,
    float* __restrict__ QPhi, float* __restrict__ KPhi)
{
    __shared__ __align__(16) uint32_t As[128*36];
    __shared__ __align__(16) uint32_t Ws[128*36];
    __shared__ float rowsq[128];
    const int hh  = blockIdx.y % 3;
    const int sel = blockIdx.y / 3;
    const float* A = (sel ? Kin : Qin) + hh * DH_;
    float* Phi     = sel ? KPhi : QPhi;

    const int bm = blockIdx.x * 128;
    const int tid  = threadIdx.x;
    const int lane = tid & 31, wid = tid >> 5;
    const int warp_m = wid >> 1, warp_n = wid & 1;
    const int gid = lane >> 2, tg = lane & 3;

    if (tid < 128) rowsq[tid] = 0.f;
    __syncthreads();

    float acc[2][8][4];
#pragma unroll
    for (int a = 0; a < 2; a++)
#pragma unroll
        for (int b = 0; b < 8; b++)
#pragma unroll
            for (int c = 0; c < 4; c++) acc[a][b][c] = 0.f;

    for (int it = 0; it < 2; it++) {
        const int k0 = it << 5;
#pragma unroll
        for (int p = 0; p < 4; p++) {
            int idx = tid + p * 256;
            int r = idx >> 3, c = (idx & 7) << 2;
            float4 v = *reinterpret_cast<const float4*>(A + (size_t)(bm + r) * D_ + k0 + c);
            atomicAdd(&rowsq[r], v.x * v.x + v.y * v.y + v.z * v.z + v.w * v.w);
            uint32_t* d = &As[r * 36 + c];
            d[0] = f2tf(v.x); d[1] = f2tf(v.y); d[2] = f2tf(v.z); d[3] = f2tf(v.w);
        }
#pragma unroll
        for (int p = 0; p < 4; p++) {
            int idx = tid + p * 256;
            int r = idx >> 3, c = (idx & 7) << 2;
            float4 v = *reinterpret_cast<const float4*>(omT + (size_t)r * DH_ + k0 + c);
            uint32_t* d = &Ws[r * 36 + c];
            d[0] = f2tf(v.x); d[1] = f2tf(v.y); d[2] = f2tf(v.z); d[3] = f2tf(v.w);
        }
        __syncthreads();
#pragma unroll
        for (int ks = 0; ks < 4; ks++) {
            const int kb = ks * 8;
            uint32_t af[2][4], bf8[8][2];
#pragma unroll
            for (int fm = 0; fm < 2; fm++) {
                int r0 = warp_m * 32 + fm * 16 + gid;
                af[fm][0] = As[r0 * 36 + kb + tg];
                af[fm][1] = As[(r0 + 8) * 36 + kb + tg];
                af[fm][2] = As[r0 * 36 + kb + tg + 4];
                af[fm][3] = As[(r0 + 8) * 36 + kb + tg + 4];
            }
#pragma unroll
            for (int fn = 0; fn < 8; fn++) {
                int n = warp_n * 64 + fn * 8 + gid;
                bf8[fn][0] = Ws[n * 36 + kb + tg];
                bf8[fn][1] = Ws[n * 36 + kb + tg + 4];
            }
#pragma unroll
            for (int fm = 0; fm < 2; fm++)
#pragma unroll
                for (int fn = 0; fn < 8; fn++) MMA_TF32(acc[fm][fn], af[fm], bf8[fn]);
        }
        __syncthreads();
    }

#pragma unroll
    for (int fm = 0; fm < 2; fm++) {
        int lbase = warp_m * 32 + fm * 16 + gid;
#pragma unroll
        for (int fn = 0; fn < 8; fn++) {
            int m = warp_n * 64 + fn * 8 + (tg << 1);
#pragma unroll
            for (int h = 0; h < 2; h++) {
                int lr = lbase + h * 8;
                int t = bm + lr;
                if (t < NT_) {
                    float off = 0.0625f * rowsq[lr];
                    float u0 = acc[fm][fn][h * 2 + 0];
                    float u1 = acc[fm][fn][h * 2 + 1];
                    float2 e1 = make_float2(expf(u0 - off) * 0.0625f, expf(u1 - off) * 0.0625f);
                    float2 e2 = make_float2(expf(-u0 - off) * 0.0625f, expf(-u1 - off) * 0.0625f);
                    size_t base = (size_t)t * 768 + hh * 256 + m;
                    *reinterpret_cast<float2*>(Phi + base)       = e1;
                    *reinterpret_cast<float2*>(Phi + base + 128) = e2;
                }
            }
        }
    }
}

// ---------------- attention apply GEMM with fused Z and 4-way KV partial sum ----
// grid (2, B*H): per (b,h) GEMM M=197, N=64, K=256.
__global__ __launch_bounds__(256) void attn_gemm_kernel(
    const float* __restrict__ Qp, const float* __restrict__ KVp,
    const float* __restrict__ Ksp, float* __restrict__ O)
{
    __shared__ __align__(16) uint32_t As[128*36];
    __shared__ __align__(16) uint32_t Ws[64*36];
    __shared__ float Kss[256];
    __shared__ float zacc[128];
    const int bh = blockIdx.y;
    const int b = bh / 3, hh = bh % 3;
    const float* A = Qp + (size_t)b * L_ * 768 + hh * 256;
    const float* W = KVp + (size_t)bh * DH_ * TM_;

    const int bm = blockIdx.x * 128;
    const int tid  = threadIdx.x;
    const int lane = tid & 31, wid = tid >> 5;
    const int warp_m = wid >> 1, warp_n = wid & 1;
    const int gid = lane >> 2, tg = lane & 3;

    if (tid < 128) zacc[tid] = 0.f;
    {
        size_t kb = (size_t)bh * TM_ + tid;
        Kss[tid] = Ksp[kb] + Ksp[kb + KSSZ] + Ksp[kb + 2 * KSSZ] + Ksp[kb + 3 * KSSZ];
    }
    __syncthreads();

    float acc[2][4][4];
#pragma unroll
    for (int a = 0; a < 2; a++)
#pragma unroll
        for (int c2 = 0; c2 < 4; c2++)
#pragma unroll
            for (int c = 0; c < 4; c++) acc[a][c2][c] = 0.f;

    float zpart[4] = {0.f, 0.f, 0.f, 0.f};

    for (int it = 0; it < 8; it++) {
        const int k0 = it << 5;
#pragma unroll
        for (int p = 0; p < 4; p++) {
            int idx = tid + p * 256;
            int r = idx >> 3, c = (idx & 7) << 2;
            int lr = bm + r;
            float4 v = (lr < L_) ? *reinterpret_cast<const float4*>(A + (size_t)lr * 768 + k0 + c)
                                 : make_float4(0.f, 0.f, 0.f, 0.f);
            zpart[p] += v.x * Kss[k0 + c] + v.y * Kss[k0 + c + 1]
                      + v.z * Kss[k0 + c + 2] + v.w * Kss[k0 + c + 3];
            uint32_t* d = &As[r * 36 + c];
            d[0] = f2tf(v.x); d[1] = f2tf(v.y); d[2] = f2tf(v.z); d[3] = f2tf(v.w);
        }
#pragma unroll
        for (int p = 0; p < 2; p++) {
            int idx = tid + p * 256;
            int r = idx >> 3, c = (idx & 7) << 2;
            const float* wp = W + (size_t)r * TM_ + k0 + c;
            float4 v0 = *reinterpret_cast<const float4*>(wp);
            float4 v1 = *reinterpret_cast<const float4*>(wp + KVSZ);
            float4 v2 = *reinterpret_cast<const float4*>(wp + 2 * KVSZ);
            float4 v3 = *reinterpret_cast<const float4*>(wp + 3 * KVSZ);
            float4 v = make_float4(v0.x + v1.x + v2.x + v3.x, v0.y + v1.y + v2.y + v3.y,
                                   v0.z + v1.z + v2.z + v3.z, v0.w + v1.w + v2.w + v3.w);
            uint32_t* d = &Ws[r * 36 + c];
            d[0] = f2tf(v.x); d[1] = f2tf(v.y); d[2] = f2tf(v.z); d[3] = f2tf(v.w);
        }
        __syncthreads();
#pragma unroll
        for (int ks = 0; ks < 4; ks++) {
            const int kb = ks * 8;
            LOAD_FRAGS(As, Ws, kb)
#pragma unroll
            for (int fm = 0; fm < 2; fm++)
#pragma unroll
                for (int fn = 0; fn < 4; fn++) MMA_TF32(acc[fm][fn], af[fm], bf[fn]);
        }
        __syncthreads();
    }

    // finish Z: width-8 shfl reduce (8 consecutive threads share a row), then atomic
#pragma unroll
    for (int p = 0; p < 4; p++) {
        float val = zpart[p];
        val += __shfl_down_sync(0xffffffffu, val, 4, 8);
        val += __shfl_down_sync(0xffffffffu, val, 2, 8);
        val += __shfl_down_sync(0xffffffffu, val, 1, 8);
        if ((tid & 7) == 0) atomicAdd(&zacc[(tid + p * 256) >> 3], val);
    }
    __syncthreads();

#pragma unroll
    for (int fm = 0; fm < 2; fm++) {
        int lbase = warp_m * 32 + fm * 16 + gid;
#pragma unroll
        for (int fn = 0; fn < 4; fn++) {
            int c = warp_n * 32 + fn * 8 + (tg << 1);
#pragma unroll
            for (int h = 0; h < 2; h++) {
                int lr2 = lbase + h * 8;
                int lrow = bm + lr2;
                if (lrow < L_) {
                    int t = b * L_ + lrow;
                    float z = 1.f / (zacc[lr2] + 1e-6f);
                    float v0 = acc[fm][fn][h * 2 + 0] * z;
                    float v1 = acc[fm][fn][h * 2 + 1] * z;
                    *reinterpret_cast<float2*>(O + (size_t)t * D_ + hh * 64 + c) = make_float2(v0, v1);
                }
            }
        }
    }
}

// ---------------- omega transpose + scale, ALL layers at once ----------------
__global__ void omt_all_kernel(const float* __restrict__ om, float* __restrict__ omT)
{
    int i = blockIdx.x * 256 + threadIdx.x;   // 12*8192
    int layer = i >> 13, w = i & 8191;
    int m = w >> 6, d = w & 63;
    omT[i] = om[(size_t)layer * 8192 + d * MM_ + m] * 0.35355339059327373f;
}

// ---------------- KV partial: grid (B,H,4), ~50 tokens per split ----------------
__global__ void kv_kernel(const float* __restrict__ Kp, const float* __restrict__ V,
                          float* __restrict__ KVp, float* __restrict__ Ksp)
{
    int b = blockIdx.x, h = blockIdx.y, s = blockIdx.z, m = threadIdx.x;  // 256 threads
    __shared__ __align__(16) float vs[4][64];
    float acc[64];
#pragma unroll
    for (int d = 0; d < 64; d++) acc[d] = 0.f;
    float ks = 0.f;
    const int j = m >> 6, d0 = m & 63;
    const int lstart = s * 50;
    const int lend = (s == 3) ? L_ : lstart + 50;
    for (int l0 = lstart; l0 < lend; l0 += 4) {
        int lj = l0 + j;
        if (lj < lend) vs[j][d0] = V[(size_t)(b * L_ + lj) * D_ + h * DH_ + d0];
        __syncthreads();
        int lim = lend - l0; if (lim > 4) lim = 4;
        for (int jj = 0; jj < lim; jj++) {
            float kp = Kp[(size_t)(b * L_ + l0 + jj) * 768 + h * 256 + m];
            ks += kp;
#pragma unroll
            for (int d4 = 0; d4 < 16; d4++) {
                float4 v4 = *reinterpret_cast<const float4*>(&vs[jj][d4 * 4]);
                acc[d4 * 4 + 0] += kp * v4.x;
                acc[d4 * 4 + 1] += kp * v4.y;
                acc[d4 * 4 + 2] += kp * v4.z;
                acc[d4 * 4 + 3] += kp * v4.w;
            }
        }
        __syncthreads();
    }
    size_t base = (size_t)s * KVSZ + (size_t)(b * H_ + h) * DH_ * TM_;
#pragma unroll
    for (int d = 0; d < 64; d++) KVp[base + (size_t)d * TM_ + m] = acc[d];
    Ksp[(size_t)s * KSSZ + (size_t)(b * H_ + h) * TM_ + m] = ks;
}

// ---------------- im2col for 16x16/stride16 conv ----------------
__global__ void im2col_kernel(const float* __restrict__ x, float* __restrict__ out)
{
    int o = blockIdx.x * 256 + threadIdx.x;
    if (o >= NP_ * 768) return;
    int kk = o % 768;
    int t  = o / 768;
    int b = t / 196, p = t % 196;
    int gh = p / 14, gw = p % 14;
    int c = kk / 256, r = kk % 256;
    int pp = r / 16, qq = r % 16;
    out[o] = x[((size_t)(b * 3 + c) * 224 + gh * 16 + pp) * 224 + gw * 16 + qq];
}

// ---------------- warp-per-row LayerNorm family (256 thr = 8 rows/block) -------
__device__ __forceinline__ void warp_stats(float s, float ss, float& mu, float& rs)
{
#pragma unroll
    for (int o = 16; o; o >>= 1) {
        s  += __shfl_xor_sync(0xffffffffu, s,  o);
        ss += __shfl_xor_sync(0xffffffffu, ss, o);
    }
    mu = s * (1.f / 192.f);
    rs = rsqrtf(ss * (1.f / 192.f) - mu * mu + 1e-5f);
}

__global__ void lnw_kernel(const float* __restrict__ X, const float* __restrict__ g,
                           const float* __restrict__ bb, float* __restrict__ Y, int nrows)
{
    int w = (blockIdx.x * 256 + threadIdx.x) >> 5;
    int lane = threadIdx.x & 31;
    if (w >= nrows) return;
    const float* xr = X + (size_t)w * D_;
    float2 a[3];
    float s = 0.f, ss = 0.f;
#pragma unroll
    for (int j = 0; j < 3; j++) {
        a[j] = *reinterpret_cast<const float2*>(xr + j * 64 + lane * 2);
        s += a[j].x + a[j].y;
        ss += a[j].x * a[j].x + a[j].y * a[j].y;
    }
    float mu, rs;
    warp_stats(s, ss, mu, rs);
    float* yr = Y + (size_t)w * D_;
#pragma unroll
    for (int j = 0; j < 3; j++) {
        float2 gg = *reinterpret_cast<const float2*>(g + j * 64 + lane * 2);
        float2 bv = *reinterpret_cast<const float2*>(bb + j * 64 + lane * 2);
        *reinterpret_cast<float2*>(yr + j * 64 + lane * 2) =
            make_float2((a[j].x - mu) * rs * gg.x + bv.x, (a[j].y - mu) * rs * gg.y + bv.y);
    }
}

__global__ void dlnw_kernel(const float* __restrict__ X,
                            const float* __restrict__ g1, const float* __restrict__ b1,
                            const float* __restrict__ g2, const float* __restrict__ b2,
                            float* __restrict__ Y, int nrows)
{
    int w = (blockIdx.x * 256 + threadIdx.x) >> 5;
    int lane = threadIdx.x & 31;
    if (w >= nrows) return;
    const float* xr = X + (size_t)w * D_;
    float2 a[3];
    float s = 0.f, ss = 0.f;
#pragma unroll
    for (int j = 0; j < 3; j++) {
        a[j] = *reinterpret_cast<const float2*>(xr + j * 64 + lane * 2);
        s += a[j].x + a[j].y;
        ss += a[j].x * a[j].x + a[j].y * a[j].y;
    }
    float mu, rs;
    warp_stats(s, ss, mu, rs);
    float s2 = 0.f, ss2 = 0.f;
#pragma unroll
    for (int j = 0; j < 3; j++) {
        float2 gg = *reinterpret_cast<const float2*>(g1 + j * 64 + lane * 2);
        float2 bv = *reinterpret_cast<const float2*>(b1 + j * 64 + lane * 2);
        a[j].x = (a[j].x - mu) * rs * gg.x + bv.x;
        a[j].y = (a[j].y - mu) * rs * gg.y + bv.y;
        s2 += a[j].x + a[j].y;
        ss2 += a[j].x * a[j].x + a[j].y * a[j].y;
    }
    warp_stats(s2, ss2, mu, rs);
    float* yr = Y + (size_t)w * D_;
#pragma unroll
    for (int j = 0; j < 3; j++) {
        float2 gg = *reinterpret_cast<const float2*>(g2 + j * 64 + lane * 2);
        float2 bv = *reinterpret_cast<const float2*>(b2 + j * 64 + lane * 2);
        *reinterpret_cast<float2*>(yr + j * 64 + lane * 2) =
            make_float2((a[j].x - mu) * rs * gg.x + bv.x, (a[j].y - mu) * rs * gg.y + bv.y);
    }
}

__global__ void ln_patch_w_kernel(const float* __restrict__ T, const float* __restrict__ g,
                                  const float* __restrict__ bb, const float* __restrict__ pos,
                                  float* __restrict__ XC)
{
    int w = (blockIdx.x * 256 + threadIdx.x) >> 5;   // row in [0, NP_)
    int lane = threadIdx.x & 31;
    if (w >= NP_) return;
    const float* xr = T + (size_t)w * D_;
    float2 a[3];
    float s = 0.f, ss = 0.f;
#pragma unroll
    for (int j = 0; j < 3; j++) {
        a[j] = *reinterpret_cast<const float2*>(xr + j * 64 + lane * 2);
        s += a[j].x + a[j].y;
        ss += a[j].x * a[j].x + a[j].y * a[j].y;
    }
    float mu, rs;
    warp_stats(s, ss, mu, rs);
    int b = w / 196, p = w % 196;
    const float* pr = pos + (size_t)(1 + p) * D_;
    float* yr = XC + ((size_t)b * L_ + 1 + p) * D_;
#pragma unroll
    for (int j = 0; j < 3; j++) {
        float2 gg = *reinterpret_cast<const float2*>(g + j * 64 + lane * 2);
        float2 bv = *reinterpret_cast<const float2*>(bb + j * 64 + lane * 2);
        float2 pp = *reinterpret_cast<const float2*>(pr + j * 64 + lane * 2);
        *reinterpret_cast<float2*>(yr + j * 64 + lane * 2) =
            make_float2((a[j].x - mu) * rs * gg.x + bv.x + pp.x,
                        (a[j].y - mu) * rs * gg.y + bv.y + pp.y);
    }
}

__global__ void cls_kernel(const float* __restrict__ cls, const float* __restrict__ pos,
                           float* __restrict__ XC)
{
    int b = blockIdx.x, tid = threadIdx.x;
    XC[(size_t)b * L_ * D_ + tid] = cls[tid] + pos[tid];
}

// ---------------- mean pool over sequence ----------------
__global__ void pool_kernel(const float* __restrict__ XC, float* __restrict__ P)
{
    int b = blockIdx.x, tid = threadIdx.x;
    float s = 0.f;
    for (int l = 0; l < L_; l++) s += XC[((size_t)b * L_ + l) * D_ + tid];
    P[(size_t)b * D_ + tid] = s * (1.f / 197.f);
}

// ---------------- launcher ----------------
extern "C" void kernel_launch(void* const* d_in, const int* in_sizes, int n_in,
                              void* d_out, int out_size)
{
    (void)in_sizes; (void)n_in; (void)out_size;
    const float* x    = (const float*)d_in[0];
    const float* pw   = (const float*)d_in[1];
    const float* pb   = (const float*)d_in[2];
    const float* peg  = (const float*)d_in[3];
    const float* peb  = (const float*)d_in[4];
    const float* cls  = (const float*)d_in[5];
    const float* pos  = (const float*)d_in[6];
    const float* Wq   = (const float*)d_in[7];
    const float* bq   = (const float*)d_in[8];
    const float* Wk   = (const float*)d_in[9];
    const float* bk   = (const float*)d_in[10];
    const float* Wv   = (const float*)d_in[11];
    const float* bv   = (const float*)d_in[12];
    const float* Wo   = (const float*)d_in[13];
    const float* bo   = (const float*)d_in[14];
    const float* l1g  = (const float*)d_in[15];
    const float* l1b  = (const float*)d_in[16];
    const float* l2g  = (const float*)d_in[17];
    const float* l2b  = (const float*)d_in[18];
    const float* lbg  = (const float*)d_in[19];
    const float* lbb  = (const float*)d_in[20];
    const float* W1   = (const float*)d_in[21];
    const float* b1   = (const float*)d_in[22];
    const float* W2   = (const float*)d_in[23];
    const float* b2   = (const float*)d_in[24];
    const float* om   = (const float*)d_in[25];
    const float* hw   = (const float*)d_in[26];
    const float* hb   = (const float*)d_in[27];
    float* out = (float*)d_out;

    float *xc, *q, *k, *v, *Qp, *Kp, *KVp, *Ksp, *at, *tp, *h1, *pl, *im, *omT;
    cudaGetSymbolAddress((void**)&xc,  g_xc);
    cudaGetSymbolAddress((void**)&q,   g_q);
    cudaGetSymbolAddress((void**)&k,   g_k);
    cudaGetSymbolAddress((void**)&v,   g_v);
    cudaGetSymbolAddress((void**)&Qp,  g_Qp);
    cudaGetSymbolAddress((void**)&Kp,  g_Kp);
    cudaGetSymbolAddress((void**)&KVp, g_KVp);
    cudaGetSymbolAddress((void**)&Ksp, g_Ksp);
    cudaGetSymbolAddress((void**)&at,  g_at);
    cudaGetSymbolAddress((void**)&tp,  g_tp);
    cudaGetSymbolAddress((void**)&h1,  g_h1);
    cudaGetSymbolAddress((void**)&pl,  g_pl);
    cudaGetSymbolAddress((void**)&im,  g_im);
    cudaGetSymbolAddress((void**)&omT, g_omT);

    // ---- one-time: all-layer omega transpose; patch embedding ----
    omt_all_kernel<<<(12 * 8192) / 256, 256>>>(om, omT);
    {
        int tot = NP_ * 768;
        im2col_kernel<<<(tot + 255) / 256, 256>>>(x, im);
        tgemm_kernel<<<dim3(3, NP_ / 128), 256>>>(im, pw, pb, nullptr, q, 768, D_, NP_, 0);
        ln_patch_w_kernel<<<(NP_ * 32 + 255) / 256, 256>>>(q, peg, peb, pos, xc);
        cls_kernel<<<B_, 192>>>(cls, pos, xc);
    }

    const dim3 gD(3, NTP_ / 128);    // Mo=192
    const dim3 gF(12, NTP_ / 128);   // Mo=768
    const int gLN = (NT_ * 32 + 255) / 256;

    for (int i = 0; i < 12; i++) {
        qkv_gemm_kernel<<<dim3(9, NTP_ / 128), 256>>>(
            xc,
            Wq + (size_t)i * D_ * D_, Wk + (size_t)i * D_ * D_, Wv + (size_t)i * D_ * D_,
            bq + i * D_, bk + i * D_, bv + i * D_, q, k, v);
        favor_gemm_kernel<<<dim3(NTP_ / 128, 6), 256>>>(q, k, omT + (size_t)i * 8192, Qp, Kp);
        kv_kernel<<<dim3(B_, H_, 4), 256>>>(Kp, v, KVp, Ksp);
        attn_gemm_kernel<<<dim3(2, B_ * H_), 256>>>(Qp, KVp, Ksp, at);
        // xc_new_pre = xc + attn @ Wo^T + bo
        tgemm_kernel<<<gD, 256>>>(at, Wo + (size_t)i * D_ * D_, bo + i * D_, xc, tp, D_, D_, NTP_, 0);
        lnw_kernel<<<gLN, 256>>>(tp, l1g + i * D_, l1b + i * D_, xc, NT_);
        // MLP
        tgemm_kernel<<<gF, 256>>>(xc, W1 + (size_t)i * FF_ * D_, b1 + i * FF_, nullptr, h1, D_, FF_, NTP_, 1);
        tgemm_kernel<<<gD, 256>>>(h1, W2 + (size_t)i * D_ * FF_, b2 + i * D_, xc, tp, FF_, D_, NTP_, 0);
        dlnw_kernel<<<gLN, 256>>>(tp, l2g + i * D_, l2b + i * D_, lbg + i * D_, lbb + i * D_, xc, NT_);

        if (i == 3 || i == 7 || i == 11) {
            int j = (i == 3) ? 0 : (i == 7) ? 1 : 2;
            pool_kernel<<<B_, 192>>>(xc, pl);
            tgemm_kernel<<<dim3(16, 1), 256>>>(pl, hw + (size_t)j * NCLS_ * D_, hb + j * NCLS_,
                                               nullptr, out + (size_t)j * B_ * NCLS_, D_, NCLS_, B_, 0);
        }
    }
}

// round 12
// speedup vs baseline: 1.0666x; 1.0666x over previous
#include <cuda_runtime.h>
#include <math.h>
#include <stdint.h>

#define B_    64
#define L_    197
#define D_    192
#define H_    3
#define MM_   128
#define TM_   256
#define NT_   (B_*L_)
#define NTP_  12672
#define FF_   768
#define NCLS_ 1000
#define NP_   (B_*196)
#define KVSZ  (B_*H_*64*TM_)
#define KSSZ  (B_*H_*TM_)
#define QW_   576

__device__ float g_xc [NTP_*D_];
__device__ float g_qkv[NTP_*QW_];
__device__ float g_Qp [NT_*H_*TM_];
__device__ float g_Kp [NT_*H_*TM_];
__device__ float g_KVp[4*KVSZ];
__device__ float g_Ksp[4*KSSZ];
__device__ float g_at [NTP_*D_];
__device__ float g_tp [NTP_*D_];
__device__ float g_h1 [NTP_*FF_];
__device__ float g_pl [128*D_];
__device__ float g_im [NP_*768];
__device__ float g_omT[12*MM_*64];
__device__ float g_Wp [12*QW_*D_];
__device__ float g_bp [12*QW_];

__device__ __forceinline__ uint32_t f2tf(float f) {
    uint32_t o; asm("cvt.rna.tf32.f32 %0, %1;" : "=r"(o) : "f"(f)); return o;
}

#define MMA_TF32(acc, af, bf)                                               \
    asm volatile(                                                           \
        "mma.sync.aligned.m16n8k8.row.col.f32.tf32.tf32.f32 "               \
        "{%0,%1,%2,%3}, {%4,%5,%6,%7}, {%8,%9}, {%0,%1,%2,%3};\n"           \
        : "+f"(acc[0]), "+f"(acc[1]), "+f"(acc[2]), "+f"(acc[3])            \
        : "r"(af[0]), "r"(af[1]), "r"(af[2]), "r"(af[3]),                   \
          "r"(bf[0]), "r"(bf[1]))

// ============ dense GEMM: 128x96 block, 4 warps, 64x48 warp tile ============
// C[.,Mo] = A[.,K] @ W[Mo,K]^T (+bias,+add,+relu). K%32==0, Mo%96==0,
// rows padded (no guards). A row stride == K.
__global__ __launch_bounds__(128) void tg96(
    const float* __restrict__ A, const float* __restrict__ W,
    const float* __restrict__ bias, const float* __restrict__ add,
    float* __restrict__ C, int K, int Mo, int relu)
{
    __shared__ __align__(16) uint32_t As[128*36];
    __shared__ __align__(16) uint32_t Ws[96*36];
    const int bm = blockIdx.y * 128;
    const int bn = blockIdx.x * 96;
    const int tid = threadIdx.x;
    const int lane = tid & 31, wid = tid >> 5;
    const int warp_m = wid >> 1, warp_n = wid & 1;
    const int gid = lane >> 2, tg = lane & 3;

    float acc[4][6][4];
#pragma unroll
    for (int a = 0; a < 4; a++)
#pragma unroll
        for (int b = 0; b < 6; b++)
#pragma unroll
            for (int c = 0; c < 4; c++) acc[a][b][c] = 0.f;

    const int niter = K >> 5;
    float4 pa[8], pw[6];
#pragma unroll
    for (int p = 0; p < 8; p++) {
        int pos = tid + p * 128;
        int r = pos >> 3, cg = pos & 7;
        pa[p] = *reinterpret_cast<const float4*>(A + (size_t)(bm + r) * K + cg * 4);
    }
#pragma unroll
    for (int p = 0; p < 6; p++) {
        int pos = tid + p * 128;
        int r = pos >> 3, cg = pos & 7;
        pw[p] = *reinterpret_cast<const float4*>(W + (size_t)(bn + r) * K + cg * 4);
    }

    for (int it = 0; it < niter; it++) {
#pragma unroll
        for (int p = 0; p < 8; p++) {
            int pos = tid + p * 128;
            int r = pos >> 3, cg = pos & 7;
            uint32_t* d = &As[r * 36 + cg * 4];
            d[0] = f2tf(pa[p].x); d[1] = f2tf(pa[p].y);
            d[2] = f2tf(pa[p].z); d[3] = f2tf(pa[p].w);
        }
#pragma unroll
        for (int p = 0; p < 6; p++) {
            int pos = tid + p * 128;
            int r = pos >> 3, cg = pos & 7;
            uint32_t* d = &Ws[r * 36 + cg * 4];
            d[0] = f2tf(pw[p].x); d[1] = f2tf(pw[p].y);
            d[2] = f2tf(pw[p].z); d[3] = f2tf(pw[p].w);
        }
        __syncthreads();

        if (it + 1 < niter) {
            int k0 = (it + 1) << 5;
#pragma unroll
            for (int p = 0; p < 8; p++) {
                int pos = tid + p * 128;
                int r = pos >> 3, cg = pos & 7;
                pa[p] = *reinterpret_cast<const float4*>(A + (size_t)(bm + r) * K + k0 + cg * 4);
            }
#pragma unroll
            for (int p = 0; p < 6; p++) {
                int pos = tid + p * 128;
                int r = pos >> 3, cg = pos & 7;
                pw[p] = *reinterpret_cast<const float4*>(W + (size_t)(bn + r) * K + k0 + cg * 4);
            }
        }

#pragma unroll
        for (int ks = 0; ks < 4; ks++) {
            const int kb = ks * 8;
            uint32_t af[4][4], bf[6][2];
#pragma unroll
            for (int fm = 0; fm < 4; fm++) {
                int r0 = warp_m * 64 + fm * 16 + gid;
                af[fm][0] = As[r0 * 36 + kb + tg];
                af[fm][1] = As[(r0 + 8) * 36 + kb + tg];
                af[fm][2] = As[r0 * 36 + kb + tg + 4];
                af[fm][3] = As[(r0 + 8) * 36 + kb + tg + 4];
            }
#pragma unroll
            for (int fn = 0; fn < 6; fn++) {
                int n = warp_n * 48 + fn * 8 + gid;
                bf[fn][0] = Ws[n * 36 + kb + tg];
                bf[fn][1] = Ws[n * 36 + kb + tg + 4];
            }
#pragma unroll
            for (int fm = 0; fm < 4; fm++)
#pragma unroll
                for (int fn = 0; fn < 6; fn++) MMA_TF32(acc[fm][fn], af[fm], bf[fn]);
        }
        __syncthreads();
    }

#pragma unroll
    for (int fm = 0; fm < 4; fm++) {
        int rbase = bm + warp_m * 64 + fm * 16 + gid;
#pragma unroll
        for (int fn = 0; fn < 6; fn++) {
            int c = bn + warp_n * 48 + fn * 8 + (tg << 1);
            float bc0 = bias[c], bc1 = bias[c + 1];
#pragma unroll
            for (int h = 0; h < 2; h++) {
                int row = rbase + h * 8;
                float v0 = acc[fm][fn][h * 2 + 0] + bc0;
                float v1 = acc[fm][fn][h * 2 + 1] + bc1;
                if (add) {
                    float2 ad = *reinterpret_cast<const float2*>(add + (size_t)row * Mo + c);
                    v0 += ad.x; v1 += ad.y;
                }
                if (relu) { v0 = fmaxf(v0, 0.f); v1 = fmaxf(v1, 0.f); }
                *reinterpret_cast<float2*>(C + (size_t)row * Mo + c) = make_float2(v0, v1);
            }
        }
    }
}

// ============ heads GEMM (128x64, guarded) ============
__global__ __launch_bounds__(256) void tgemm_kernel(
    const float* __restrict__ A, const float* __restrict__ W,
    const float* __restrict__ bias, float* __restrict__ C,
    int K, int Mo, int Nstore)
{
    __shared__ __align__(16) uint32_t As[128*36];
    __shared__ __align__(16) uint32_t Ws[64*36];
    const int bm = blockIdx.y * 128, bn = blockIdx.x * 64;
    const int tid = threadIdx.x, lane = tid & 31, wid = tid >> 5;
    const int warp_m = wid >> 1, warp_n = wid & 1;
    const int gid = lane >> 2, tg = lane & 3;
    float acc[2][4][4];
#pragma unroll
    for (int a = 0; a < 2; a++)
#pragma unroll
        for (int b = 0; b < 4; b++)
#pragma unroll
            for (int c = 0; c < 4; c++) acc[a][b][c] = 0.f;
    for (int it = 0; it < (K >> 5); it++) {
        int k0 = it << 5;
#pragma unroll
        for (int p = 0; p < 4; p++) {
            int idx = tid + p * 256;
            int r = idx >> 3, c = (idx & 7) << 2;
            float4 v = *reinterpret_cast<const float4*>(A + (size_t)(bm + r) * K + k0 + c);
            uint32_t* d = &As[r * 36 + c];
            d[0]=f2tf(v.x); d[1]=f2tf(v.y); d[2]=f2tf(v.z); d[3]=f2tf(v.w);
        }
#pragma unroll
        for (int p = 0; p < 2; p++) {
            int idx = tid + p * 256;
            int r = idx >> 3, c = (idx & 7) << 2;
            int wr = bn + r;
            float4 v = (wr < Mo) ? *reinterpret_cast<const float4*>(W + (size_t)wr * K + k0 + c)
                                 : make_float4(0.f,0.f,0.f,0.f);
            uint32_t* d = &Ws[r * 36 + c];
            d[0]=f2tf(v.x); d[1]=f2tf(v.y); d[2]=f2tf(v.z); d[3]=f2tf(v.w);
        }
        __syncthreads();
#pragma unroll
        for (int ks = 0; ks < 4; ks++) {
            const int kb = ks * 8;
            uint32_t af[2][4], bf[4][2];
#pragma unroll
            for (int fm = 0; fm < 2; fm++) {
                int r0 = warp_m * 32 + fm * 16 + gid;
                af[fm][0] = As[r0*36+kb+tg];   af[fm][1] = As[(r0+8)*36+kb+tg];
                af[fm][2] = As[r0*36+kb+tg+4]; af[fm][3] = As[(r0+8)*36+kb+tg+4];
            }
#pragma unroll
            for (int fn = 0; fn < 4; fn++) {
                int n = warp_n * 32 + fn * 8 + gid;
                bf[fn][0] = Ws[n*36+kb+tg]; bf[fn][1] = Ws[n*36+kb+tg+4];
            }
#pragma unroll
            for (int fm = 0; fm < 2; fm++)
#pragma unroll
                for (int fn = 0; fn < 4; fn++) MMA_TF32(acc[fm][fn], af[fm], bf[fn]);
        }
        __syncthreads();
    }
#pragma unroll
    for (int fm = 0; fm < 2; fm++) {
        int rbase = bm + warp_m * 32 + fm * 16 + gid;
#pragma unroll
        for (int fn = 0; fn < 4; fn++) {
            int c = bn + warp_n * 32 + fn * 8 + (tg << 1);
            if (c < Mo) {
                float bc0 = bias[c], bc1 = bias[c+1];
#pragma unroll
                for (int h = 0; h < 2; h++) {
                    int row = rbase + h * 8;
                    if (row < Nstore)
                        *reinterpret_cast<float2*>(C + (size_t)row * Mo + c) =
                            make_float2(acc[fm][fn][h*2]+bc0, acc[fm][fn][h*2+1]+bc1);
                }
            }
        }
    }
}

// ---------------- FAVOR GEMM (packed qkv, stride 576) ----------------
__global__ __launch_bounds__(256) void favor_gemm_kernel(
    const float* __restrict__ QKV, const float* __restrict__ omT,
    float* __restrict__ QPhi, float* __restrict__ KPhi)
{
    __shared__ __align__(16) uint32_t As[128*36];
    __shared__ __align__(16) uint32_t Ws[128*36];
    __shared__ float rowsq[128];
    const int hh = blockIdx.y % 3, sel = blockIdx.y / 3;
    const float* A = QKV + sel * 192 + hh * 64;
    float* Phi = sel ? KPhi : QPhi;
    const int bm = blockIdx.x * 128;
    const int tid = threadIdx.x, lane = tid & 31, wid = tid >> 5;
    const int warp_m = wid >> 1, warp_n = wid & 1;
    const int gid = lane >> 2, tg = lane & 3;

    if (tid < 128) rowsq[tid] = 0.f;
    __syncthreads();

    float acc[2][8][4];
#pragma unroll
    for (int a = 0; a < 2; a++)
#pragma unroll
        for (int b = 0; b < 8; b++)
#pragma unroll
            for (int c = 0; c < 4; c++) acc[a][b][c] = 0.f;

    for (int it = 0; it < 2; it++) {
        const int k0 = it << 5;
#pragma unroll
        for (int p = 0; p < 4; p++) {
            int idx = tid + p * 256;
            int r = idx >> 3, c = (idx & 7) << 2;
            float4 v = *reinterpret_cast<const float4*>(A + (size_t)(bm + r) * QW_ + k0 + c);
            atomicAdd(&rowsq[r], v.x*v.x + v.y*v.y + v.z*v.z + v.w*v.w);
            uint32_t* d = &As[r * 36 + c];
            d[0]=f2tf(v.x); d[1]=f2tf(v.y); d[2]=f2tf(v.z); d[3]=f2tf(v.w);
        }
#pragma unroll
        for (int p = 0; p < 4; p++) {
            int idx = tid + p * 256;
            int r = idx >> 3, c = (idx & 7) << 2;
            float4 v = *reinterpret_cast<const float4*>(omT + (size_t)r * 64 + k0 + c);
            uint32_t* d = &Ws[r * 36 + c];
            d[0]=f2tf(v.x); d[1]=f2tf(v.y); d[2]=f2tf(v.z); d[3]=f2tf(v.w);
        }
        __syncthreads();
#pragma unroll
        for (int ks = 0; ks < 4; ks++) {
            const int kb = ks * 8;
            uint32_t af[2][4], bf8[8][2];
#pragma unroll
            for (int fm = 0; fm < 2; fm++) {
                int r0 = warp_m * 32 + fm * 16 + gid;
                af[fm][0] = As[r0*36+kb+tg];   af[fm][1] = As[(r0+8)*36+kb+tg];
                af[fm][2] = As[r0*36+kb+tg+4]; af[fm][3] = As[(r0+8)*36+kb+tg+4];
            }
#pragma unroll
            for (int fn = 0; fn < 8; fn++) {
                int n = warp_n * 64 + fn * 8 + gid;
                bf8[fn][0] = Ws[n*36+kb+tg]; bf8[fn][1] = Ws[n*36+kb+tg+4];
            }
#pragma unroll
            for (int fm = 0; fm < 2; fm++)
#pragma unroll
                for (int fn = 0; fn < 8; fn++) MMA_TF32(acc[fm][fn], af[fm], bf8[fn]);
        }
        __syncthreads();
    }

#pragma unroll
    for (int fm = 0; fm < 2; fm++) {
        int lbase = warp_m * 32 + fm * 16 + gid;
#pragma unroll
        for (int fn = 0; fn < 8; fn++) {
            int m = warp_n * 64 + fn * 8 + (tg << 1);
#pragma unroll
            for (int h = 0; h < 2; h++) {
                int lr = lbase + h * 8;
                int t = bm + lr;
                if (t < NT_) {
                    float off = 0.0625f * rowsq[lr];
                    float u0 = acc[fm][fn][h*2], u1 = acc[fm][fn][h*2+1];
                    size_t base = (size_t)t * 768 + hh * 256 + m;
                    *reinterpret_cast<float2*>(Phi + base) =
                        make_float2(expf(u0-off)*0.0625f, expf(u1-off)*0.0625f);
                    *reinterpret_cast<float2*>(Phi + base + 128) =
                        make_float2(expf(-u0-off)*0.0625f, expf(-u1-off)*0.0625f);
                }
            }
        }
    }
}

// ---------------- attention apply GEMM (fused Z, 4-way KV partial sum) ----------
__global__ __launch_bounds__(256) void attn_gemm_kernel(
    const float* __restrict__ Qp, const float* __restrict__ KVp,
    const float* __restrict__ Ksp, float* __restrict__ O)
{
    __shared__ __align__(16) uint32_t As[128*36];
    __shared__ __align__(16) uint32_t Ws[64*36];
    __shared__ float Kss[256];
    __shared__ float zacc[128];
    const int bh = blockIdx.y, b = bh / 3, hh = bh % 3;
    const float* A = Qp + (size_t)b * L_ * 768 + hh * 256;
    const float* W = KVp + (size_t)bh * 64 * TM_;
    const int bm = blockIdx.x * 128;
    const int tid = threadIdx.x, lane = tid & 31, wid = tid >> 5;
    const int warp_m = wid >> 1, warp_n = wid & 1;
    const int gid = lane >> 2, tg = lane & 3;

    if (tid < 128) zacc[tid] = 0.f;
    {
        size_t kb = (size_t)bh * TM_ + tid;
        Kss[tid] = Ksp[kb] + Ksp[kb+KSSZ] + Ksp[kb+2*KSSZ] + Ksp[kb+3*KSSZ];
    }
    __syncthreads();

    float acc[2][4][4];
#pragma unroll
    for (int a = 0; a < 2; a++)
#pragma unroll
        for (int c2 = 0; c2 < 4; c2++)
#pragma unroll
            for (int c = 0; c < 4; c++) acc[a][c2][c] = 0.f;
    float zpart[4] = {0.f, 0.f, 0.f, 0.f};

    for (int it = 0; it < 8; it++) {
        const int k0 = it << 5;
#pragma unroll
        for (int p = 0; p < 4; p++) {
            int idx = tid + p * 256;
            int r = idx >> 3, c = (idx & 7) << 2;
            int lr = bm + r;
            float4 v = (lr < L_) ? *reinterpret_cast<const float4*>(A + (size_t)lr * 768 + k0 + c)
                                 : make_float4(0.f,0.f,0.f,0.f);
            zpart[p] += v.x*Kss[k0+c] + v.y*Kss[k0+c+1] + v.z*Kss[k0+c+2] + v.w*Kss[k0+c+3];
            uint32_t* d = &As[r * 36 + c];
            d[0]=f2tf(v.x); d[1]=f2tf(v.y); d[2]=f2tf(v.z); d[3]=f2tf(v.w);
        }
#pragma unroll
        for (int p = 0; p < 2; p++) {
            int idx = tid + p * 256;
            int r = idx >> 3, c = (idx & 7) << 2;
            const float* wp = W + (size_t)r * TM_ + k0 + c;
            float4 v0 = *reinterpret_cast<const float4*>(wp);
            float4 v1 = *reinterpret_cast<const float4*>(wp + KVSZ);
            float4 v2 = *reinterpret_cast<const float4*>(wp + 2*KVSZ);
            float4 v3 = *reinterpret_cast<const float4*>(wp + 3*KVSZ);
            uint32_t* d = &Ws[r * 36 + c];
            d[0]=f2tf(v0.x+v1.x+v2.x+v3.x); d[1]=f2tf(v0.y+v1.y+v2.y+v3.y);
            d[2]=f2tf(v0.z+v1.z+v2.z+v3.z); d[3]=f2tf(v0.w+v1.w+v2.w+v3.w);
        }
        __syncthreads();
#pragma unroll
        for (int ks = 0; ks < 4; ks++) {
            const int kb = ks * 8;
            uint32_t af[2][4], bf[4][2];
#pragma unroll
            for (int fm = 0; fm < 2; fm++) {
                int r0 = warp_m * 32 + fm * 16 + gid;
                af[fm][0] = As[r0*36+kb+tg];   af[fm][1] = As[(r0+8)*36+kb+tg];
                af[fm][2] = As[r0*36+kb+tg+4]; af[fm][3] = As[(r0+8)*36+kb+tg+4];
            }
#pragma unroll
            for (int fn = 0; fn < 4; fn++) {
                int n = warp_n * 32 + fn * 8 + gid;
                bf[fn][0] = Ws[n*36+kb+tg]; bf[fn][1] = Ws[n*36+kb+tg+4];
            }
#pragma unroll
            for (int fm = 0; fm < 2; fm++)
#pragma unroll
                for (int fn = 0; fn < 4; fn++) MMA_TF32(acc[fm][fn], af[fm], bf[fn]);
        }
        __syncthreads();
    }

#pragma unroll
    for (int p = 0; p < 4; p++) {
        float val = zpart[p];
        val += __shfl_down_sync(0xffffffffu, val, 4, 8);
        val += __shfl_down_sync(0xffffffffu, val, 2, 8);
        val += __shfl_down_sync(0xffffffffu, val, 1, 8);
        if ((tid & 7) == 0) atomicAdd(&zacc[(tid + p * 256) >> 3], val);
    }
    __syncthreads();

#pragma unroll
    for (int fm = 0; fm < 2; fm++) {
        int lbase = warp_m * 32 + fm * 16 + gid;
#pragma unroll
        for (int fn = 0; fn < 4; fn++) {
            int c = warp_n * 32 + fn * 8 + (tg << 1);
#pragma unroll
            for (int h = 0; h < 2; h++) {
                int lr2 = lbase + h * 8;
                int lrow = bm + lr2;
                if (lrow < L_) {
                    int t = b * L_ + lrow;
                    float z = 1.f / (zacc[lr2] + 1e-6f);
                    *reinterpret_cast<float2*>(O + (size_t)t * D_ + hh * 64 + c) =
                        make_float2(acc[fm][fn][h*2]*z, acc[fm][fn][h*2+1]*z);
                }
            }
        }
    }
}

// ---------------- one-time prep ----------------
__global__ void omt_all_kernel(const float* __restrict__ om, float* __restrict__ omT)
{
    int i = blockIdx.x * 256 + threadIdx.x;
    int layer = i >> 13, w = i & 8191;
    int m = w >> 6, d = w & 63;
    omT[i] = om[(size_t)layer * 8192 + d * MM_ + m] * 0.35355339059327373f;
}

__global__ void pack_qkv_kernel(
    const float* __restrict__ Wq, const float* __restrict__ Wk, const float* __restrict__ Wv,
    const float* __restrict__ bq, const float* __restrict__ bk, const float* __restrict__ bv,
    float* __restrict__ Wp, float* __restrict__ bp)
{
    size_t i = (size_t)blockIdx.x * 256 + threadIdx.x;
    if (i < (size_t)12 * QW_ * D_) {
        int col = (int)(i % D_);
        size_t rr = i / D_;
        int row = (int)(rr % QW_), layer = (int)(rr / QW_);
        int sel = row / D_, r = row % D_;
        const float* W = (sel == 0) ? Wq : (sel == 1) ? Wk : Wv;
        Wp[i] = W[((size_t)layer * D_ + r) * D_ + col];
    }
    if (i < (size_t)12 * QW_) {
        int row = (int)(i % QW_), layer = (int)(i / QW_);
        int sel = row / D_, r = row % D_;
        const float* bb = (sel == 0) ? bq : (sel == 1) ? bk : bv;
        bp[i] = bb[layer * D_ + r];
    }
}

// ---------------- KV partial: grid (B,H,4) ----------------
__global__ void kv_kernel(const float* __restrict__ Kp, const float* __restrict__ QKV,
                          float* __restrict__ KVp, float* __restrict__ Ksp)
{
    int b = blockIdx.x, h = blockIdx.y, s = blockIdx.z, m = threadIdx.x;
    __shared__ __align__(16) float vs[4][64];
    float acc[64];
#pragma unroll
    for (int d = 0; d < 64; d++) acc[d] = 0.f;
    float ks = 0.f;
    const int j = m >> 6, d0 = m & 63;
    const int lstart = s * 50;
    const int lend = (s == 3) ? L_ : lstart + 50;
    for (int l0 = lstart; l0 < lend; l0 += 4) {
        int lj = l0 + j;
        if (lj < lend) vs[j][d0] = QKV[(size_t)(b * L_ + lj) * QW_ + 384 + h * 64 + d0];
        __syncthreads();
        int lim = lend - l0; if (lim > 4) lim = 4;
        for (int jj = 0; jj < lim; jj++) {
            float kp = Kp[(size_t)(b * L_ + l0 + jj) * 768 + h * 256 + m];
            ks += kp;
#pragma unroll
            for (int d4 = 0; d4 < 16; d4++) {
                float4 v4 = *reinterpret_cast<const float4*>(&vs[jj][d4 * 4]);
                acc[d4*4+0] += kp*v4.x; acc[d4*4+1] += kp*v4.y;
                acc[d4*4+2] += kp*v4.z; acc[d4*4+3] += kp*v4.w;
            }
        }
        __syncthreads();
    }
    size_t base = (size_t)s * KVSZ + (size_t)(b * H_ + h) * 64 * TM_;
#pragma unroll
    for (int d = 0; d < 64; d++) KVp[base + (size_t)d * TM_ + m] = acc[d];
    Ksp[(size_t)s * KSSZ + (size_t)(b * H_ + h) * TM_ + m] = ks;
}

// ---------------- im2col ----------------
__global__ void im2col_kernel(const float* __restrict__ x, float* __restrict__ out)
{
    int o = blockIdx.x * 256 + threadIdx.x;
    if (o >= NP_ * 768) return;
    int kk = o % 768, t = o / 768;
    int b = t / 196, p = t % 196;
    int gh = p / 14, gw = p % 14;
    int c = kk / 256, r = kk % 256;
    int pp = r / 16, qq = r % 16;
    out[o] = x[((size_t)(b * 3 + c) * 224 + gh * 16 + pp) * 224 + gw * 16 + qq];
}

// ---------------- warp-per-row LayerNorm ----------------
__device__ __forceinline__ void warp_stats(float s, float ss, float& mu, float& rs)
{
#pragma unroll
    for (int o = 16; o; o >>= 1) {
        s  += __shfl_xor_sync(0xffffffffu, s,  o);
        ss += __shfl_xor_sync(0xffffffffu, ss, o);
    }
    mu = s * (1.f / 192.f);
    rs = rsqrtf(ss * (1.f / 192.f) - mu * mu + 1e-5f);
}

__global__ void lnw_kernel(const float* __restrict__ X, const float* __restrict__ g,
                           const float* __restrict__ bb, float* __restrict__ Y, int nrows)
{
    int w = (blockIdx.x * 256 + threadIdx.x) >> 5;
    int lane = threadIdx.x & 31;
    if (w >= nrows) return;
    const float* xr = X + (size_t)w * D_;
    float2 a[3];
    float s = 0.f, ss = 0.f;
#pragma unroll
    for (int j = 0; j < 3; j++) {
        a[j] = *reinterpret_cast<const float2*>(xr + j * 64 + lane * 2);
        s += a[j].x + a[j].y;
        ss += a[j].x * a[j].x + a[j].y * a[j].y;
    }
    float mu, rs;
    warp_stats(s, ss, mu, rs);
    float* yr = Y + (size_t)w * D_;
#pragma unroll
    for (int j = 0; j < 3; j++) {
        float2 gg = *reinterpret_cast<const float2*>(g + j * 64 + lane * 2);
        float2 bv = *reinterpret_cast<const float2*>(bb + j * 64 + lane * 2);
        *reinterpret_cast<float2*>(yr + j * 64 + lane * 2) =
            make_float2((a[j].x - mu) * rs * gg.x + bv.x, (a[j].y - mu) * rs * gg.y + bv.y);
    }
}

__global__ void dlnw_kernel(const float* __restrict__ X,
                            const float* __restrict__ g1, const float* __restrict__ b1,
                            const float* __restrict__ g2, const float* __restrict__ b2,
                            float* __restrict__ Y, int nrows)
{
    int w = (blockIdx.x * 256 + threadIdx.x) >> 5;
    int lane = threadIdx.x & 31;
    if (w >= nrows) return;
    const float* xr = X + (size_t)w * D_;
    float2 a[3];
    float s = 0.f, ss = 0.f;
#pragma unroll
    for (int j = 0; j < 3; j++) {
        a[j] = *reinterpret_cast<const float2*>(xr + j * 64 + lane * 2);
        s += a[j].x + a[j].y;
        ss += a[j].x * a[j].x + a[j].y * a[j].y;
    }
    float mu, rs;
    warp_stats(s, ss, mu, rs);
    float s2 = 0.f, ss2 = 0.f;
#pragma unroll
    for (int j = 0; j < 3; j++) {
        float2 gg = *reinterpret_cast<const float2*>(g1 + j * 64 + lane * 2);
        float2 bv = *reinterpret_cast<const float2*>(b1 + j * 64 + lane * 2);
        a[j].x = (a[j].x - mu) * rs * gg.x + bv.x;
        a[j].y = (a[j].y - mu) * rs * gg.y + bv.y;
        s2 += a[j].x + a[j].y;
        ss2 += a[j].x * a[j].x + a[j].y * a[j].y;
    }
    warp_stats(s2, ss2, mu, rs);
    float* yr = Y + (size_t)w * D_;
#pragma unroll
    for (int j = 0; j < 3; j++) {
        float2 gg = *reinterpret_cast<const float2*>(g2 + j * 64 + lane * 2);
        float2 bv = *reinterpret_cast<const float2*>(b2 + j * 64 + lane * 2);
        *reinterpret_cast<float2*>(yr + j * 64 + lane * 2) =
            make_float2((a[j].x - mu) * rs * gg.x + bv.x, (a[j].y - mu) * rs * gg.y + bv.y);
    }
}

__global__ void ln_patch_w_kernel(const float* __restrict__ T, const float* __restrict__ g,
                                  const float* __restrict__ bb, const float* __restrict__ pos,
                                  float* __restrict__ XC)
{
    int w = (blockIdx.x * 256 + threadIdx.x) >> 5;
    int lane = threadIdx.x & 31;
    if (w >= NP_) return;
    const float* xr = T + (size_t)w * D_;
    float2 a[3];
    float s = 0.f, ss = 0.f;
#pragma unroll
    for (int j = 0; j < 3; j++) {
        a[j] = *reinterpret_cast<const float2*>(xr + j * 64 + lane * 2);
        s += a[j].x + a[j].y;
        ss += a[j].x * a[j].x + a[j].y * a[j].y;
    }
    float mu, rs;
    warp_stats(s, ss, mu, rs);
    int b = w / 196, p = w % 196;
    const float* pr = pos + (size_t)(1 + p) * D_;
    float* yr = XC + ((size_t)b * L_ + 1 + p) * D_;
#pragma unroll
    for (int j = 0; j < 3; j++) {
        float2 gg = *reinterpret_cast<const float2*>(g + j * 64 + lane * 2);
        float2 bv = *reinterpret_cast<const float2*>(bb + j * 64 + lane * 2);
        float2 pp = *reinterpret_cast<const float2*>(pr + j * 64 + lane * 2);
        *reinterpret_cast<float2*>(yr + j * 64 + lane * 2) =
            make_float2((a[j].x - mu) * rs * gg.x + bv.x + pp.x,
                        (a[j].y - mu) * rs * gg.y + bv.y + pp.y);
    }
}

__global__ void cls_kernel(const float* __restrict__ cls, const float* __restrict__ pos,
                           float* __restrict__ XC)
{
    int b = blockIdx.x, tid = threadIdx.x;
    XC[(size_t)b * L_ * D_ + tid] = cls[tid] + pos[tid];
}

__global__ void pool_kernel(const float* __restrict__ XC, float* __restrict__ P)
{
    int b = blockIdx.x, tid = threadIdx.x;
    float s = 0.f;
    for (int l = 0; l < L_; l++) s += XC[((size_t)b * L_ + l) * D_ + tid];
    P[(size_t)b * D_ + tid] = s * (1.f / 197.f);
}

// ---------------- launcher ----------------
extern "C" void kernel_launch(void* const* d_in, const int* in_sizes, int n_in,
                              void* d_out, int out_size)
{
    (void)in_sizes; (void)n_in; (void)out_size;
    const float* x    = (const float*)d_in[0];
    const float* pw   = (const float*)d_in[1];
    const float* pb   = (const float*)d_in[2];
    const float* peg  = (const float*)d_in[3];
    const float* peb  = (const float*)d_in[4];
    const float* cls  = (const float*)d_in[5];
    const float* pos  = (const float*)d_in[6];
    const float* Wq   = (const float*)d_in[7];
    const float* bq   = (const float*)d_in[8];
    const float* Wk   = (const float*)d_in[9];
    const float* bk   = (const float*)d_in[10];
    const float* Wv   = (const float*)d_in[11];
    const float* bv   = (const float*)d_in[12];
    const float* Wo   = (const float*)d_in[13];
    const float* bo   = (const float*)d_in[14];
    const float* l1g  = (const float*)d_in[15];
    const float* l1b  = (const float*)d_in[16];
    const float* l2g  = (const float*)d_in[17];
    const float* l2b  = (const float*)d_in[18];
    const float* lbg  = (const float*)d_in[19];
    const float* lbb  = (const float*)d_in[20];
    const float* W1   = (const float*)d_in[21];
    const float* b1   = (const float*)d_in[22];
    const float* W2   = (const float*)d_in[23];
    const float* b2   = (const float*)d_in[24];
    const float* om   = (const float*)d_in[25];
    const float* hw   = (const float*)d_in[26];
    const float* hb   = (const float*)d_in[27];
    float* out = (float*)d_out;

    float *xc, *qkv, *Qp, *Kp, *KVp, *Ksp, *at, *tp, *h1, *pl, *im, *omT, *Wp, *bp;
    cudaGetSymbolAddress((void**)&xc,  g_xc);
    cudaGetSymbolAddress((void**)&qkv, g_qkv);
    cudaGetSymbolAddress((void**)&Qp,  g_Qp);
    cudaGetSymbolAddress((void**)&Kp,  g_Kp);
    cudaGetSymbolAddress((void**)&KVp, g_KVp);
    cudaGetSymbolAddress((void**)&Ksp, g_Ksp);
    cudaGetSymbolAddress((void**)&at,  g_at);
    cudaGetSymbolAddress((void**)&tp,  g_tp);
    cudaGetSymbolAddress((void**)&h1,  g_h1);
    cudaGetSymbolAddress((void**)&pl,  g_pl);
    cudaGetSymbolAddress((void**)&im,  g_im);
    cudaGetSymbolAddress((void**)&omT, g_omT);
    cudaGetSymbolAddress((void**)&Wp,  g_Wp);
    cudaGetSymbolAddress((void**)&bp,  g_bp);

    omt_all_kernel<<<(12 * 8192) / 256, 256>>>(om, omT);
    pack_qkv_kernel<<<(12 * QW_ * D_ + 255) / 256, 256>>>(Wq, Wk, Wv, bq, bk, bv, Wp, bp);
    {
        int tot = NP_ * 768;
        im2col_kernel<<<(tot + 255) / 256, 256>>>(x, im);
        tg96<<<dim3(2, NP_ / 128), 128>>>(im, pw, pb, nullptr, tp, 768, D_, 0);
        ln_patch_w_kernel<<<(NP_ * 32 + 255) / 256, 256>>>(tp, peg, peb, pos, xc);
        cls_kernel<<<B_, 192>>>(cls, pos, xc);
    }

    const int gLN = (NT_ * 32 + 255) / 256;
    for (int i = 0; i < 12; i++) {
        tg96<<<dim3(6, NTP_ / 128), 128>>>(xc, Wp + (size_t)i * QW_ * D_, bp + i * QW_,
                                           nullptr, qkv, D_, QW_, 0);
        favor_gemm_kernel<<<dim3(NTP_ / 128, 6), 256>>>(qkv, omT + (size_t)i * 8192, Qp, Kp);
        kv_kernel<<<dim3(B_, H_, 4), 256>>>(Kp, qkv, KVp, Ksp);
        attn_gemm_kernel<<<dim3(2, B_ * H_), 256>>>(Qp, KVp, Ksp, at);
        tg96<<<dim3(2, NTP_ / 128), 128>>>(at, Wo + (size_t)i * D_ * D_, bo + i * D_,
                                           xc, tp, D_, D_, 0);
        lnw_kernel<<<gLN, 256>>>(tp, l1g + i * D_, l1b + i * D_, xc, NT_);
        tg96<<<dim3(8, NTP_ / 128), 128>>>(xc, W1 + (size_t)i * FF_ * D_, b1 + i * FF_,
                                           nullptr, h1, D_, FF_, 1);
        tg96<<<dim3(2, NTP_ / 128), 128>>>(h1, W2 + (size_t)i * D_ * FF_, b2 + i * D_,
                                           xc, tp, FF_, D_, 0);
        dlnw_kernel<<<gLN, 256>>>(tp, l2g + i * D_, l2b + i * D_, lbg + i * D_, lbb + i * D_, xc, NT_);

        if (i == 3 || i == 7 || i == 11) {
            int j = (i == 3) ? 0 : (i == 7) ? 1 : 2;
            pool_kernel<<<B_, 192>>>(xc, pl);
            tgemm_kernel<<<dim3(16, 1), 256>>>(pl, hw + (size_t)j * NCLS_ * D_, hb + j * NCLS_,
                                               out + (size_t)j * B_ * NCLS_, D_, NCLS_, B_);
        }
    }
}